// round 2
// baseline (speedup 1.0000x reference)
#include <cuda_runtime.h>
#include <cuda_bf16.h>
#include <cstdint>

// Problem constants
#define NHEAD  16
#define LSEQ   2048
#define DMODEL 1024
#define DHEAD  64
#define NBATCH 2
#define MROWS  (NBATCH * LSEQ)   // 4096
#define NCOLS  (NHEAD * DHEAD)   // 1024

// -------- scratch (device globals; no allocations allowed) --------
__device__ float g_qp[(size_t)NBATCH * NHEAD * LSEQ * DHEAD];   // [b][h][l][c] 16MB
__device__ float g_kp[(size_t)NBATCH * NHEAD * LSEQ * DHEAD];
__device__ float g_vp[(size_t)NBATCH * NHEAD * LSEQ * DHEAD];
__device__ float g_gate[(size_t)MROWS * NCOLS];                 // [b*l][h*64+c]
__device__ float g_att[(size_t)MROWS * NCOLS];                  // gated weighted avg

// -------- helpers --------
__device__ __forceinline__ float tf32r(float x) {
    uint32_t u;
    asm("cvt.rna.tf32.f32 %0, %1;" : "=r"(u) : "f"(x));
    return __uint_as_float(u);
}

__device__ __forceinline__ void mma8(float& d0, float& d1, float& d2, float& d3,
                                     uint32_t a0, uint32_t a1, uint32_t a2, uint32_t a3,
                                     uint32_t b0, uint32_t b1) {
    asm volatile(
        "mma.sync.aligned.m16n8k8.row.col.f32.tf32.tf32.f32 "
        "{%0,%1,%2,%3}, {%4,%5,%6,%7}, {%8,%9}, {%0,%1,%2,%3};\n"
        : "+f"(d0), "+f"(d1), "+f"(d2), "+f"(d3)
        : "r"(a0), "r"(a1), "r"(a2), "r"(a3), "r"(b0), "r"(b1));
}

// ================= Projection GEMM =================
// C[M=4096, N=1024] = X[M,1024] * W[1024,1024], tf32 mma, fp32 accum.
// blockIdx.z: 0=q(scale), 1=k, 2=v, 3=gate(sigmoid(x+g_bias))
#define GBM 128
#define GBN 64
#define GBK 16
#define APITCH (GBK + 4)   // 20
#define BPITCH (GBN + 4)   // 68

__global__ __launch_bounds__(256)
void proj_kernel(const float* __restrict__ Qin, const float* __restrict__ Kin,
                 const float* __restrict__ Vin,
                 const float* __restrict__ Wq, const float* __restrict__ Wk,
                 const float* __restrict__ Wv, const float* __restrict__ Wg,
                 const float* __restrict__ gbias)
{
    __shared__ float As[GBM * APITCH];
    __shared__ float Bs[GBK * BPITCH];

    const int z = blockIdx.z;
    const float* X = (z == 1) ? Kin : ((z == 2) ? Vin : Qin);
    const float* W = (z == 0) ? Wq : ((z == 1) ? Wk : ((z == 2) ? Wv : Wg));

    const int row0 = blockIdx.y * GBM;
    const int col0 = blockIdx.x * GBN;
    const int tid  = threadIdx.x;
    const int lane = tid & 31, wid = tid >> 5;
    const int g = lane >> 2, t = lane & 3;
    const int warp_m = wid & 3, warp_n = wid >> 2;   // 4x2 warp grid, 32x32 tiles

    float acc[2][4][4];
#pragma unroll
    for (int mt = 0; mt < 2; ++mt)
#pragma unroll
        for (int nt = 0; nt < 4; ++nt)
#pragma unroll
            for (int e = 0; e < 4; ++e) acc[mt][nt][e] = 0.f;

    for (int k0 = 0; k0 < DMODEL; k0 += GBK) {
        // load A tile 128x16 (2 float4 per thread), round to tf32
#pragma unroll
        for (int i = 0; i < 2; ++i) {
            int idx = tid + i * 256;             // 0..511
            int r = idx >> 2, kq = (idx & 3) * 4;
            float4 v4 = *reinterpret_cast<const float4*>(
                &X[(size_t)(row0 + r) * DMODEL + k0 + kq]);
            float* dst = &As[r * APITCH + kq];
            dst[0] = tf32r(v4.x); dst[1] = tf32r(v4.y);
            dst[2] = tf32r(v4.z); dst[3] = tf32r(v4.w);
        }
        // load B tile 16x64 (1 float4 per thread)
        {
            int kk = tid >> 4, nq = (tid & 15) * 4;
            float4 v4 = *reinterpret_cast<const float4*>(
                &W[(size_t)(k0 + kk) * NCOLS + col0 + nq]);
            float* dst = &Bs[kk * BPITCH + nq];
            dst[0] = tf32r(v4.x); dst[1] = tf32r(v4.y);
            dst[2] = tf32r(v4.z); dst[3] = tf32r(v4.w);
        }
        __syncthreads();

#pragma unroll
        for (int kc = 0; kc < GBK; kc += 8) {
            uint32_t af[2][4], bf[4][2];
#pragma unroll
            for (int mt = 0; mt < 2; ++mt) {
                int rb = warp_m * 32 + mt * 16;
                af[mt][0] = __float_as_uint(As[(rb + g) * APITCH + kc + t]);
                af[mt][1] = __float_as_uint(As[(rb + 8 + g) * APITCH + kc + t]);
                af[mt][2] = __float_as_uint(As[(rb + g) * APITCH + kc + t + 4]);
                af[mt][3] = __float_as_uint(As[(rb + 8 + g) * APITCH + kc + t + 4]);
            }
#pragma unroll
            for (int nt = 0; nt < 4; ++nt) {
                int cb = warp_n * 32 + nt * 8;
                bf[nt][0] = __float_as_uint(Bs[(kc + t) * BPITCH + cb + g]);
                bf[nt][1] = __float_as_uint(Bs[(kc + t + 4) * BPITCH + cb + g]);
            }
#pragma unroll
            for (int mt = 0; mt < 2; ++mt)
#pragma unroll
                for (int nt = 0; nt < 4; ++nt)
                    mma8(acc[mt][nt][0], acc[mt][nt][1], acc[mt][nt][2], acc[mt][nt][3],
                         af[mt][0], af[mt][1], af[mt][2], af[mt][3],
                         bf[nt][0], bf[nt][1]);
        }
        __syncthreads();
    }

    // epilogue
    const float scale = 0.125f;   // dk^-0.5
#pragma unroll
    for (int mt = 0; mt < 2; ++mt) {
#pragma unroll
        for (int nt = 0; nt < 4; ++nt) {
            int rg0 = row0 + warp_m * 32 + mt * 16 + g;
            int cg  = col0 + warp_n * 32 + nt * 8 + 2 * t;
            int rr[4] = {rg0, rg0, rg0 + 8, rg0 + 8};
            int cc[4] = {cg, cg + 1, cg, cg + 1};
#pragma unroll
            for (int e = 0; e < 4; ++e) {
                int row = rr[e], col = cc[e];
                float v = acc[mt][nt][e];
                if (z <= 2) {
                    if (z == 0) v *= scale;
                    int bb = row >> 11, l = row & (LSEQ - 1);
                    int hh = col >> 6,  cx = col & (DHEAD - 1);
                    float* dst = (z == 0) ? g_qp : ((z == 1) ? g_kp : g_vp);
                    dst[((((size_t)bb * NHEAD + hh) * LSEQ) + l) * DHEAD + cx] = tf32r(v);
                } else {
                    float xg = v + gbias[col];
                    g_gate[(size_t)row * NCOLS + col] = 1.f / (1.f + __expf(-xg));
                }
            }
        }
    }
}

// ================= Flash attention =================
// Per block: 128 q-rows of one (b,h). Streams 64-wide k-tiles.
// softmax denominator uses ALL entries (post-softmax masking); numerator masked.
#define BQ  128
#define BKT 64
#define SP  68   // smem row pitch for 64-wide tiles
#define ATTN_SMEM_FLOATS (BQ*SP + BKT*SP + BKT*SP + BQ*SP + 3*BQ)
#define ATTN_SMEM_BYTES  (ATTN_SMEM_FLOATS * 4)

__global__ __launch_bounds__(256)
void attn_kernel(const float* __restrict__ bias, const int* __restrict__ mask)
{
    extern __shared__ float smem[];
    float* q_s  = smem;                 // [128][68]
    float* k_s  = q_s + BQ * SP;        // [64][68]  (K transposed: [c][kk])
    float* v_s  = k_s + BKT * SP;       // [64][68]  ([kk][c])
    float* s_s  = v_s + BKT * SP;       // [128][68] S then P
    float* m_sm = s_s + BQ * SP;
    float* l_sm = m_sm + BQ;
    float* al_sm = l_sm + BQ;

    const int b = blockIdx.z, h = blockIdx.y;
    const int q0 = blockIdx.x * BQ;
    const int tid = threadIdx.x;
    const int lane = tid & 31, wid = tid >> 5;
    const int g = lane >> 2, t = lane & 3;
    const int warp_m = wid & 3, warp_n = wid >> 2;
    const float LOG2E = 1.4426950408889634f;

    // load q tile (already scaled + tf32-rounded by proj)
    const float* qbase = g_qp + (((size_t)b * NHEAD + h) * LSEQ + q0) * DHEAD;
#pragma unroll
    for (int i = 0; i < 8; ++i) {
        int idx = tid + i * 256;               // 0..2047 float4s
        int r = idx >> 4, cq = (idx & 15) * 4;
        float4 v4 = *reinterpret_cast<const float4*>(&qbase[(size_t)r * DHEAD + cq]);
        float* dst = &q_s[r * SP + cq];
        dst[0] = v4.x; dst[1] = v4.y; dst[2] = v4.z; dst[3] = v4.w;
    }
    if (tid < BQ) { m_sm[tid] = -1e30f; l_sm[tid] = 0.f; }

    float acc[2][4][4];
#pragma unroll
    for (int mt = 0; mt < 2; ++mt)
#pragma unroll
        for (int nt = 0; nt < 4; ++nt)
#pragma unroll
            for (int e = 0; e < 4; ++e) acc[mt][nt][e] = 0.f;

    for (int kt = 0; kt < LSEQ / BKT; ++kt) {
        __syncthreads();   // q ready (iter 0) / previous PV done
        const int k0 = kt * BKT;
        const float* kb = g_kp + (((size_t)b * NHEAD + h) * LSEQ + k0) * DHEAD;
        const float* vb = g_vp + (((size_t)b * NHEAD + h) * LSEQ + k0) * DHEAD;

        // K tile transposed: k_s[c][kk]
#pragma unroll
        for (int i = 0; i < 16; ++i) {
            int idx = tid + i * 256;
            int kk = idx >> 6, c = idx & 63;
            k_s[c * SP + kk] = kb[(size_t)kk * DHEAD + c];
        }
        // V tile: v_s[kk][c]
#pragma unroll
        for (int i = 0; i < 4; ++i) {
            int idx = tid + i * 256;
            int kk = idx >> 4, cq = (idx & 15) * 4;
            float4 v4 = *reinterpret_cast<const float4*>(&vb[(size_t)kk * DHEAD + cq]);
            float* dst = &v_s[kk * SP + cq];
            dst[0] = v4.x; dst[1] = v4.y; dst[2] = v4.z; dst[3] = v4.w;
        }
        __syncthreads();

        // ---- S = q * k^T ----
        float sacc[2][4][4];
#pragma unroll
        for (int mt = 0; mt < 2; ++mt)
#pragma unroll
            for (int nt = 0; nt < 4; ++nt)
#pragma unroll
                for (int e = 0; e < 4; ++e) sacc[mt][nt][e] = 0.f;

#pragma unroll
        for (int kc = 0; kc < DHEAD; kc += 8) {
            uint32_t af[2][4], bf[4][2];
#pragma unroll
            for (int mt = 0; mt < 2; ++mt) {
                int rb = warp_m * 32 + mt * 16;
                af[mt][0] = __float_as_uint(q_s[(rb + g) * SP + kc + t]);
                af[mt][1] = __float_as_uint(q_s[(rb + 8 + g) * SP + kc + t]);
                af[mt][2] = __float_as_uint(q_s[(rb + g) * SP + kc + t + 4]);
                af[mt][3] = __float_as_uint(q_s[(rb + 8 + g) * SP + kc + t + 4]);
            }
#pragma unroll
            for (int nt = 0; nt < 4; ++nt) {
                int cb = warp_n * 32 + nt * 8;
                bf[nt][0] = __float_as_uint(k_s[(kc + t) * SP + cb + g]);
                bf[nt][1] = __float_as_uint(k_s[(kc + t + 4) * SP + cb + g]);
            }
#pragma unroll
            for (int mt = 0; mt < 2; ++mt)
#pragma unroll
                for (int nt = 0; nt < 4; ++nt)
                    mma8(sacc[mt][nt][0], sacc[mt][nt][1], sacc[mt][nt][2], sacc[mt][nt][3],
                         af[mt][0], af[mt][1], af[mt][2], af[mt][3],
                         bf[nt][0], bf[nt][1]);
        }
        // write S to smem
#pragma unroll
        for (int mt = 0; mt < 2; ++mt) {
            int rb = warp_m * 32 + mt * 16;
#pragma unroll
            for (int nt = 0; nt < 4; ++nt) {
                int cb = warp_n * 32 + nt * 8;
                s_s[(rb + g) * SP + cb + 2 * t]         = sacc[mt][nt][0];
                s_s[(rb + g) * SP + cb + 2 * t + 1]     = sacc[mt][nt][1];
                s_s[(rb + 8 + g) * SP + cb + 2 * t]     = sacc[mt][nt][2];
                s_s[(rb + 8 + g) * SP + cb + 2 * t + 1] = sacc[mt][nt][3];
            }
        }
        __syncthreads();

        // ---- bias + online softmax + post-softmax mask (mask is int32!) ----
        {
            int r  = tid >> 1;
            int hf = tid & 1;
            size_t off = (((size_t)b * NHEAD + h) * LSEQ + (q0 + r)) * (size_t)LSEQ
                         + k0 + hf * 32;
            const float* brow = bias + off;
            float f[32];
            float mx = -1e30f;
#pragma unroll
            for (int j = 0; j < 8; ++j) {
                float4 b4 = reinterpret_cast<const float4*>(brow)[j];
                int c = hf * 32 + j * 4;
                f[j * 4 + 0] = s_s[r * SP + c + 0] + b4.x;
                f[j * 4 + 1] = s_s[r * SP + c + 1] + b4.y;
                f[j * 4 + 2] = s_s[r * SP + c + 2] + b4.z;
                f[j * 4 + 3] = s_s[r * SP + c + 3] + b4.w;
                mx = fmaxf(mx, fmaxf(fmaxf(f[j*4], f[j*4+1]), fmaxf(f[j*4+2], f[j*4+3])));
            }
            mx = fmaxf(mx, __shfl_xor_sync(0xffffffffu, mx, 1));
            float m_old = m_sm[r];
            float m_new = fmaxf(m_old, mx);
            float alpha = exp2f((m_old - m_new) * LOG2E);

            const int4* mrow = reinterpret_cast<const int4*>(mask + off);
            float lsum = 0.f;
#pragma unroll
            for (int j4 = 0; j4 < 8; ++j4) {
                int4 mi = mrow[j4];
                int cb = hf * 32 + j4 * 4;
                float p0 = exp2f((f[j4*4+0] - m_new) * LOG2E);
                float p1 = exp2f((f[j4*4+1] - m_new) * LOG2E);
                float p2 = exp2f((f[j4*4+2] - m_new) * LOG2E);
                float p3 = exp2f((f[j4*4+3] - m_new) * LOG2E);
                lsum += (p0 + p1) + (p2 + p3);          // denominator: ALL entries
                s_s[r * SP + cb + 0] = tf32r(mi.x ? p0 : 0.f);  // numerator masked
                s_s[r * SP + cb + 1] = tf32r(mi.y ? p1 : 0.f);
                s_s[r * SP + cb + 2] = tf32r(mi.z ? p2 : 0.f);
                s_s[r * SP + cb + 3] = tf32r(mi.w ? p3 : 0.f);
            }
            lsum += __shfl_xor_sync(0xffffffffu, lsum, 1);
            if (hf == 0) {
                l_sm[r] = l_sm[r] * alpha + lsum;
                m_sm[r] = m_new;
                al_sm[r] = alpha;
            }
        }
        __syncthreads();

        // ---- rescale acc, then acc += P * V ----
#pragma unroll
        for (int mt = 0; mt < 2; ++mt) {
            int rb = warp_m * 32 + mt * 16;
            float a0 = al_sm[rb + g], a1 = al_sm[rb + 8 + g];
#pragma unroll
            for (int nt = 0; nt < 4; ++nt) {
                acc[mt][nt][0] *= a0; acc[mt][nt][1] *= a0;
                acc[mt][nt][2] *= a1; acc[mt][nt][3] *= a1;
            }
        }
#pragma unroll
        for (int kc = 0; kc < BKT; kc += 8) {
            uint32_t af[2][4], bf[4][2];
#pragma unroll
            for (int mt = 0; mt < 2; ++mt) {
                int rb = warp_m * 32 + mt * 16;
                af[mt][0] = __float_as_uint(s_s[(rb + g) * SP + kc + t]);
                af[mt][1] = __float_as_uint(s_s[(rb + 8 + g) * SP + kc + t]);
                af[mt][2] = __float_as_uint(s_s[(rb + g) * SP + kc + t + 4]);
                af[mt][3] = __float_as_uint(s_s[(rb + 8 + g) * SP + kc + t + 4]);
            }
#pragma unroll
            for (int nt = 0; nt < 4; ++nt) {
                int cb = warp_n * 32 + nt * 8;
                bf[nt][0] = __float_as_uint(v_s[(kc + t) * SP + cb + g]);
                bf[nt][1] = __float_as_uint(v_s[(kc + t + 4) * SP + cb + g]);
            }
#pragma unroll
            for (int mt = 0; mt < 2; ++mt)
#pragma unroll
                for (int nt = 0; nt < 4; ++nt)
                    mma8(acc[mt][nt][0], acc[mt][nt][1], acc[mt][nt][2], acc[mt][nt][3],
                         af[mt][0], af[mt][1], af[mt][2], af[mt][3],
                         bf[nt][0], bf[nt][1]);
        }
    }

    // ---- epilogue: /l, *gate, store ----
#pragma unroll
    for (int mt = 0; mt < 2; ++mt) {
#pragma unroll
        for (int nt = 0; nt < 4; ++nt) {
            int rl0 = warp_m * 32 + mt * 16 + g;
            int cb  = warp_n * 32 + nt * 8 + 2 * t;
            float inv0 = 1.f / l_sm[rl0];
            float inv1 = 1.f / l_sm[rl0 + 8];
            size_t base0 = ((size_t)(b * LSEQ + q0 + rl0)) * NCOLS + h * DHEAD;
            size_t base1 = ((size_t)(b * LSEQ + q0 + rl0 + 8)) * NCOLS + h * DHEAD;
            g_att[base0 + cb]     = acc[mt][nt][0] * inv0 * g_gate[base0 + cb];
            g_att[base0 + cb + 1] = acc[mt][nt][1] * inv0 * g_gate[base0 + cb + 1];
            g_att[base1 + cb]     = acc[mt][nt][2] * inv1 * g_gate[base1 + cb];
            g_att[base1 + cb + 1] = acc[mt][nt][3] * inv1 * g_gate[base1 + cb + 1];
        }
    }
}

// ================= Output projection =================
__global__ __launch_bounds__(256)
void oproj_kernel(const float* __restrict__ Wo, const float* __restrict__ obias,
                  float* __restrict__ out)
{
    __shared__ float As[GBM * APITCH];
    __shared__ float Bs[GBK * BPITCH];

    const int row0 = blockIdx.y * GBM;
    const int col0 = blockIdx.x * GBN;
    const int tid = threadIdx.x;
    const int lane = tid & 31, wid = tid >> 5;
    const int g = lane >> 2, t = lane & 3;
    const int warp_m = wid & 3, warp_n = wid >> 2;

    float acc[2][4][4];
#pragma unroll
    for (int mt = 0; mt < 2; ++mt)
#pragma unroll
        for (int nt = 0; nt < 4; ++nt)
#pragma unroll
            for (int e = 0; e < 4; ++e) acc[mt][nt][e] = 0.f;

    for (int k0 = 0; k0 < NCOLS; k0 += GBK) {
#pragma unroll
        for (int i = 0; i < 2; ++i) {
            int idx = tid + i * 256;
            int r = idx >> 2, kq = (idx & 3) * 4;
            float4 v4 = *reinterpret_cast<const float4*>(
                &g_att[(size_t)(row0 + r) * NCOLS + k0 + kq]);
            float* dst = &As[r * APITCH + kq];
            dst[0] = tf32r(v4.x); dst[1] = tf32r(v4.y);
            dst[2] = tf32r(v4.z); dst[3] = tf32r(v4.w);
        }
        {
            int kk = tid >> 4, nq = (tid & 15) * 4;
            float4 v4 = *reinterpret_cast<const float4*>(
                &Wo[(size_t)(k0 + kk) * DMODEL + col0 + nq]);
            float* dst = &Bs[kk * BPITCH + nq];
            dst[0] = tf32r(v4.x); dst[1] = tf32r(v4.y);
            dst[2] = tf32r(v4.z); dst[3] = tf32r(v4.w);
        }
        __syncthreads();

#pragma unroll
        for (int kc = 0; kc < GBK; kc += 8) {
            uint32_t af[2][4], bf[4][2];
#pragma unroll
            for (int mt = 0; mt < 2; ++mt) {
                int rb = warp_m * 32 + mt * 16;
                af[mt][0] = __float_as_uint(As[(rb + g) * APITCH + kc + t]);
                af[mt][1] = __float_as_uint(As[(rb + 8 + g) * APITCH + kc + t]);
                af[mt][2] = __float_as_uint(As[(rb + g) * APITCH + kc + t + 4]);
                af[mt][3] = __float_as_uint(As[(rb + 8 + g) * APITCH + kc + t + 4]);
            }
#pragma unroll
            for (int nt = 0; nt < 4; ++nt) {
                int cb = warp_n * 32 + nt * 8;
                bf[nt][0] = __float_as_uint(Bs[(kc + t) * BPITCH + cb + g]);
                bf[nt][1] = __float_as_uint(Bs[(kc + t + 4) * BPITCH + cb + g]);
            }
#pragma unroll
            for (int mt = 0; mt < 2; ++mt)
#pragma unroll
                for (int nt = 0; nt < 4; ++nt)
                    mma8(acc[mt][nt][0], acc[mt][nt][1], acc[mt][nt][2], acc[mt][nt][3],
                         af[mt][0], af[mt][1], af[mt][2], af[mt][3],
                         bf[nt][0], bf[nt][1]);
        }
        __syncthreads();
    }

#pragma unroll
    for (int mt = 0; mt < 2; ++mt) {
#pragma unroll
        for (int nt = 0; nt < 4; ++nt) {
            int rg0 = row0 + warp_m * 32 + mt * 16 + g;
            int cg  = col0 + warp_n * 32 + nt * 8 + 2 * t;
            out[(size_t)rg0 * DMODEL + cg]           = acc[mt][nt][0] + obias[cg];
            out[(size_t)rg0 * DMODEL + cg + 1]       = acc[mt][nt][1] + obias[cg + 1];
            out[(size_t)(rg0 + 8) * DMODEL + cg]     = acc[mt][nt][2] + obias[cg];
            out[(size_t)(rg0 + 8) * DMODEL + cg + 1] = acc[mt][nt][3] + obias[cg + 1];
        }
    }
}

// ================= launcher =================
extern "C" void kernel_launch(void* const* d_in, const int* in_sizes, int n_in,
                              void* d_out, int out_size)
{
    const float*   Q    = (const float*)d_in[0];
    const float*   K    = (const float*)d_in[1];
    const float*   V    = (const float*)d_in[2];
    const float*   bias = (const float*)d_in[3];
    const int*     mask = (const int*)d_in[4];
    const float*   qw   = (const float*)d_in[5];
    const float*   kw   = (const float*)d_in[6];
    const float*   vw   = (const float*)d_in[7];
    const float*   gw   = (const float*)d_in[8];
    const float*   gb   = (const float*)d_in[9];
    const float*   ow   = (const float*)d_in[10];
    const float*   ob   = (const float*)d_in[11];
    float* out = (float*)d_out;

    cudaFuncSetAttribute(attn_kernel, cudaFuncAttributeMaxDynamicSharedMemorySize,
                         ATTN_SMEM_BYTES);

    dim3 gp(NCOLS / GBN, MROWS / GBM, 4);      // 16 x 32 x 4
    proj_kernel<<<gp, 256>>>(Q, K, V, qw, kw, vw, gw, gb);

    dim3 ga(LSEQ / BQ, NHEAD, NBATCH);         // 16 x 16 x 2
    attn_kernel<<<ga, 256, ATTN_SMEM_BYTES>>>(bias, mask);

    dim3 go(DMODEL / GBN, MROWS / GBM, 1);     // 16 x 32
    oproj_kernel<<<go, 256>>>(ow, ob, out);
}

// round 3
// speedup vs baseline: 1.0016x; 1.0016x over previous
#include <cuda_runtime.h>
#include <cuda_bf16.h>
#include <cstdint>

// Problem constants
#define NHEAD  16
#define LSEQ   2048
#define DMODEL 1024
#define DHEAD  64
#define NBATCH 2
#define MROWS  (NBATCH * LSEQ)   // 4096
#define NCOLS  (NHEAD * DHEAD)   // 1024

// -------- scratch (device globals; no allocations allowed) --------
__device__ float g_qp[(size_t)NBATCH * NHEAD * LSEQ * DHEAD];   // [b][h][l][c] 16MB
__device__ float g_kp[(size_t)NBATCH * NHEAD * LSEQ * DHEAD];
__device__ float g_vp[(size_t)NBATCH * NHEAD * LSEQ * DHEAD];
__device__ float g_gate[(size_t)MROWS * NCOLS];                 // [b*l][h*64+c]
__device__ float g_att[(size_t)MROWS * NCOLS];                  // gated weighted avg

// -------- helpers --------
__device__ __forceinline__ float tf32r(float x) {
    uint32_t u;
    asm("cvt.rna.tf32.f32 %0, %1;" : "=r"(u) : "f"(x));
    return __uint_as_float(u);
}

__device__ __forceinline__ void mma8(float& d0, float& d1, float& d2, float& d3,
                                     uint32_t a0, uint32_t a1, uint32_t a2, uint32_t a3,
                                     uint32_t b0, uint32_t b1) {
    asm volatile(
        "mma.sync.aligned.m16n8k8.row.col.f32.tf32.tf32.f32 "
        "{%0,%1,%2,%3}, {%4,%5,%6,%7}, {%8,%9}, {%0,%1,%2,%3};\n"
        : "+f"(d0), "+f"(d1), "+f"(d2), "+f"(d3)
        : "r"(a0), "r"(a1), "r"(a2), "r"(a3), "r"(b0), "r"(b1));
}

// ================= Projection GEMM =================
// C[M=4096, N=1024] = X[M,1024] * W[1024,1024], tf32 mma, fp32 accum.
// blockIdx.z: 0=q(scale), 1=k, 2=v, 3=gate(sigmoid(x+g_bias))
#define GBM 128
#define GBN 64
#define GBK 16
#define APITCH (GBK + 4)   // 20
#define BPITCH (GBN + 4)   // 68

__global__ __launch_bounds__(256)
void proj_kernel(const float* __restrict__ Qin, const float* __restrict__ Kin,
                 const float* __restrict__ Vin,
                 const float* __restrict__ Wq, const float* __restrict__ Wk,
                 const float* __restrict__ Wv, const float* __restrict__ Wg,
                 const float* __restrict__ gbias)
{
    __shared__ float As[GBM * APITCH];
    __shared__ float Bs[GBK * BPITCH];

    const int z = blockIdx.z;
    const float* X = (z == 1) ? Kin : ((z == 2) ? Vin : Qin);
    const float* W = (z == 0) ? Wq : ((z == 1) ? Wk : ((z == 2) ? Wv : Wg));

    const int row0 = blockIdx.y * GBM;
    const int col0 = blockIdx.x * GBN;
    const int tid  = threadIdx.x;
    const int lane = tid & 31, wid = tid >> 5;
    const int g = lane >> 2, t = lane & 3;
    const int warp_m = wid & 3, warp_n = wid >> 2;   // 4x2 warp grid, 32x32 tiles

    float acc[2][4][4];
#pragma unroll
    for (int mt = 0; mt < 2; ++mt)
#pragma unroll
        for (int nt = 0; nt < 4; ++nt)
#pragma unroll
            for (int e = 0; e < 4; ++e) acc[mt][nt][e] = 0.f;

    for (int k0 = 0; k0 < DMODEL; k0 += GBK) {
        // load A tile 128x16 (2 float4 per thread), round to tf32
#pragma unroll
        for (int i = 0; i < 2; ++i) {
            int idx = tid + i * 256;             // 0..511
            int r = idx >> 2, kq = (idx & 3) * 4;
            float4 v4 = *reinterpret_cast<const float4*>(
                &X[(size_t)(row0 + r) * DMODEL + k0 + kq]);
            float* dst = &As[r * APITCH + kq];
            dst[0] = tf32r(v4.x); dst[1] = tf32r(v4.y);
            dst[2] = tf32r(v4.z); dst[3] = tf32r(v4.w);
        }
        // load B tile 16x64 (1 float4 per thread)
        {
            int kk = tid >> 4, nq = (tid & 15) * 4;
            float4 v4 = *reinterpret_cast<const float4*>(
                &W[(size_t)(k0 + kk) * NCOLS + col0 + nq]);
            float* dst = &Bs[kk * BPITCH + nq];
            dst[0] = tf32r(v4.x); dst[1] = tf32r(v4.y);
            dst[2] = tf32r(v4.z); dst[3] = tf32r(v4.w);
        }
        __syncthreads();

#pragma unroll
        for (int kc = 0; kc < GBK; kc += 8) {
            uint32_t af[2][4], bf[4][2];
#pragma unroll
            for (int mt = 0; mt < 2; ++mt) {
                int rb = warp_m * 32 + mt * 16;
                af[mt][0] = __float_as_uint(As[(rb + g) * APITCH + kc + t]);
                af[mt][1] = __float_as_uint(As[(rb + 8 + g) * APITCH + kc + t]);
                af[mt][2] = __float_as_uint(As[(rb + g) * APITCH + kc + t + 4]);
                af[mt][3] = __float_as_uint(As[(rb + 8 + g) * APITCH + kc + t + 4]);
            }
#pragma unroll
            for (int nt = 0; nt < 4; ++nt) {
                int cb = warp_n * 32 + nt * 8;
                bf[nt][0] = __float_as_uint(Bs[(kc + t) * BPITCH + cb + g]);
                bf[nt][1] = __float_as_uint(Bs[(kc + t + 4) * BPITCH + cb + g]);
            }
#pragma unroll
            for (int mt = 0; mt < 2; ++mt)
#pragma unroll
                for (int nt = 0; nt < 4; ++nt)
                    mma8(acc[mt][nt][0], acc[mt][nt][1], acc[mt][nt][2], acc[mt][nt][3],
                         af[mt][0], af[mt][1], af[mt][2], af[mt][3],
                         bf[nt][0], bf[nt][1]);
        }
        __syncthreads();
    }

    // epilogue
    const float scale = 0.125f;   // dk^-0.5
#pragma unroll
    for (int mt = 0; mt < 2; ++mt) {
#pragma unroll
        for (int nt = 0; nt < 4; ++nt) {
            int rg0 = row0 + warp_m * 32 + mt * 16 + g;
            int cg  = col0 + warp_n * 32 + nt * 8 + 2 * t;
            int rr[4] = {rg0, rg0, rg0 + 8, rg0 + 8};
            int cc[4] = {cg, cg + 1, cg, cg + 1};
#pragma unroll
            for (int e = 0; e < 4; ++e) {
                int row = rr[e], col = cc[e];
                float v = acc[mt][nt][e];
                if (z <= 2) {
                    if (z == 0) v *= scale;
                    int bb = row >> 11, l = row & (LSEQ - 1);
                    int hh = col >> 6,  cx = col & (DHEAD - 1);
                    float* dst = (z == 0) ? g_qp : ((z == 1) ? g_kp : g_vp);
                    dst[((((size_t)bb * NHEAD + hh) * LSEQ) + l) * DHEAD + cx] = tf32r(v);
                } else {
                    float xg = v + gbias[col];
                    g_gate[(size_t)row * NCOLS + col] = 1.f / (1.f + __expf(-xg));
                }
            }
        }
    }
}

// ================= Flash attention =================
// Per block: 128 q-rows of one (b,h). Streams 64-wide k-tiles.
// softmax denominator uses ALL entries (post-softmax masking); numerator masked.
#define BQ  128
#define BKT 64
#define SP  68   // smem row pitch for 64-wide tiles
#define ATTN_SMEM_FLOATS (BQ*SP + BKT*SP + BKT*SP + BQ*SP + 3*BQ)
#define ATTN_SMEM_BYTES  (ATTN_SMEM_FLOATS * 4)

__global__ __launch_bounds__(256)
void attn_kernel(const float* __restrict__ bias, const int* __restrict__ mask)
{
    extern __shared__ float smem[];
    float* q_s  = smem;                 // [128][68]
    float* k_s  = q_s + BQ * SP;        // [64][68]  (K transposed: [c][kk])
    float* v_s  = k_s + BKT * SP;       // [64][68]  ([kk][c])
    float* s_s  = v_s + BKT * SP;       // [128][68] S then P
    float* m_sm = s_s + BQ * SP;
    float* l_sm = m_sm + BQ;
    float* al_sm = l_sm + BQ;

    const int b = blockIdx.z, h = blockIdx.y;
    const int q0 = blockIdx.x * BQ;
    const int tid = threadIdx.x;
    const int lane = tid & 31, wid = tid >> 5;
    const int g = lane >> 2, t = lane & 3;
    const int warp_m = wid & 3, warp_n = wid >> 2;
    const float LOG2E = 1.4426950408889634f;

    // load q tile (already scaled + tf32-rounded by proj)
    const float* qbase = g_qp + (((size_t)b * NHEAD + h) * LSEQ + q0) * DHEAD;
#pragma unroll
    for (int i = 0; i < 8; ++i) {
        int idx = tid + i * 256;               // 0..2047 float4s
        int r = idx >> 4, cq = (idx & 15) * 4;
        float4 v4 = *reinterpret_cast<const float4*>(&qbase[(size_t)r * DHEAD + cq]);
        float* dst = &q_s[r * SP + cq];
        dst[0] = v4.x; dst[1] = v4.y; dst[2] = v4.z; dst[3] = v4.w;
    }
    if (tid < BQ) { m_sm[tid] = -1e30f; l_sm[tid] = 0.f; }

    float acc[2][4][4];
#pragma unroll
    for (int mt = 0; mt < 2; ++mt)
#pragma unroll
        for (int nt = 0; nt < 4; ++nt)
#pragma unroll
            for (int e = 0; e < 4; ++e) acc[mt][nt][e] = 0.f;

    for (int kt = 0; kt < LSEQ / BKT; ++kt) {
        __syncthreads();   // q ready (iter 0) / previous PV done
        const int k0 = kt * BKT;
        const float* kb = g_kp + (((size_t)b * NHEAD + h) * LSEQ + k0) * DHEAD;
        const float* vb = g_vp + (((size_t)b * NHEAD + h) * LSEQ + k0) * DHEAD;

        // K tile transposed: k_s[c][kk]
#pragma unroll
        for (int i = 0; i < 16; ++i) {
            int idx = tid + i * 256;
            int kk = idx >> 6, c = idx & 63;
            k_s[c * SP + kk] = kb[(size_t)kk * DHEAD + c];
        }
        // V tile: v_s[kk][c]
#pragma unroll
        for (int i = 0; i < 4; ++i) {
            int idx = tid + i * 256;
            int kk = idx >> 4, cq = (idx & 15) * 4;
            float4 v4 = *reinterpret_cast<const float4*>(&vb[(size_t)kk * DHEAD + cq]);
            float* dst = &v_s[kk * SP + cq];
            dst[0] = v4.x; dst[1] = v4.y; dst[2] = v4.z; dst[3] = v4.w;
        }
        __syncthreads();

        // ---- S = q * k^T ----
        float sacc[2][4][4];
#pragma unroll
        for (int mt = 0; mt < 2; ++mt)
#pragma unroll
            for (int nt = 0; nt < 4; ++nt)
#pragma unroll
                for (int e = 0; e < 4; ++e) sacc[mt][nt][e] = 0.f;

#pragma unroll
        for (int kc = 0; kc < DHEAD; kc += 8) {
            uint32_t af[2][4], bf[4][2];
#pragma unroll
            for (int mt = 0; mt < 2; ++mt) {
                int rb = warp_m * 32 + mt * 16;
                af[mt][0] = __float_as_uint(q_s[(rb + g) * SP + kc + t]);
                af[mt][1] = __float_as_uint(q_s[(rb + 8 + g) * SP + kc + t]);
                af[mt][2] = __float_as_uint(q_s[(rb + g) * SP + kc + t + 4]);
                af[mt][3] = __float_as_uint(q_s[(rb + 8 + g) * SP + kc + t + 4]);
            }
#pragma unroll
            for (int nt = 0; nt < 4; ++nt) {
                int cb = warp_n * 32 + nt * 8;
                bf[nt][0] = __float_as_uint(k_s[(kc + t) * SP + cb + g]);
                bf[nt][1] = __float_as_uint(k_s[(kc + t + 4) * SP + cb + g]);
            }
#pragma unroll
            for (int mt = 0; mt < 2; ++mt)
#pragma unroll
                for (int nt = 0; nt < 4; ++nt)
                    mma8(sacc[mt][nt][0], sacc[mt][nt][1], sacc[mt][nt][2], sacc[mt][nt][3],
                         af[mt][0], af[mt][1], af[mt][2], af[mt][3],
                         bf[nt][0], bf[nt][1]);
        }
        // write S to smem
#pragma unroll
        for (int mt = 0; mt < 2; ++mt) {
            int rb = warp_m * 32 + mt * 16;
#pragma unroll
            for (int nt = 0; nt < 4; ++nt) {
                int cb = warp_n * 32 + nt * 8;
                s_s[(rb + g) * SP + cb + 2 * t]         = sacc[mt][nt][0];
                s_s[(rb + g) * SP + cb + 2 * t + 1]     = sacc[mt][nt][1];
                s_s[(rb + 8 + g) * SP + cb + 2 * t]     = sacc[mt][nt][2];
                s_s[(rb + 8 + g) * SP + cb + 2 * t + 1] = sacc[mt][nt][3];
            }
        }
        __syncthreads();

        // ---- bias + online softmax + post-softmax mask (mask is int32!) ----
        {
            int r  = tid >> 1;
            int hf = tid & 1;
            size_t off = (((size_t)b * NHEAD + h) * LSEQ + (q0 + r)) * (size_t)LSEQ
                         + k0 + hf * 32;
            const float* brow = bias + off;
            float f[32];
            float mx = -1e30f;
#pragma unroll
            for (int j = 0; j < 8; ++j) {
                float4 b4 = reinterpret_cast<const float4*>(brow)[j];
                int c = hf * 32 + j * 4;
                f[j * 4 + 0] = s_s[r * SP + c + 0] + b4.x;
                f[j * 4 + 1] = s_s[r * SP + c + 1] + b4.y;
                f[j * 4 + 2] = s_s[r * SP + c + 2] + b4.z;
                f[j * 4 + 3] = s_s[r * SP + c + 3] + b4.w;
                mx = fmaxf(mx, fmaxf(fmaxf(f[j*4], f[j*4+1]), fmaxf(f[j*4+2], f[j*4+3])));
            }
            mx = fmaxf(mx, __shfl_xor_sync(0xffffffffu, mx, 1));
            float m_old = m_sm[r];
            float m_new = fmaxf(m_old, mx);
            float alpha = exp2f((m_old - m_new) * LOG2E);

            const int4* mrow = reinterpret_cast<const int4*>(mask + off);
            float lsum = 0.f;
#pragma unroll
            for (int j4 = 0; j4 < 8; ++j4) {
                int4 mi = mrow[j4];
                int cb = hf * 32 + j4 * 4;
                float p0 = exp2f((f[j4*4+0] - m_new) * LOG2E);
                float p1 = exp2f((f[j4*4+1] - m_new) * LOG2E);
                float p2 = exp2f((f[j4*4+2] - m_new) * LOG2E);
                float p3 = exp2f((f[j4*4+3] - m_new) * LOG2E);
                lsum += (p0 + p1) + (p2 + p3);          // denominator: ALL entries
                s_s[r * SP + cb + 0] = tf32r(mi.x ? p0 : 0.f);  // numerator masked
                s_s[r * SP + cb + 1] = tf32r(mi.y ? p1 : 0.f);
                s_s[r * SP + cb + 2] = tf32r(mi.z ? p2 : 0.f);
                s_s[r * SP + cb + 3] = tf32r(mi.w ? p3 : 0.f);
            }
            lsum += __shfl_xor_sync(0xffffffffu, lsum, 1);
            if (hf == 0) {
                l_sm[r] = l_sm[r] * alpha + lsum;
                m_sm[r] = m_new;
                al_sm[r] = alpha;
            }
        }
        __syncthreads();

        // ---- rescale acc, then acc += P * V ----
#pragma unroll
        for (int mt = 0; mt < 2; ++mt) {
            int rb = warp_m * 32 + mt * 16;
            float a0 = al_sm[rb + g], a1 = al_sm[rb + 8 + g];
#pragma unroll
            for (int nt = 0; nt < 4; ++nt) {
                acc[mt][nt][0] *= a0; acc[mt][nt][1] *= a0;
                acc[mt][nt][2] *= a1; acc[mt][nt][3] *= a1;
            }
        }
#pragma unroll
        for (int kc = 0; kc < BKT; kc += 8) {
            uint32_t af[2][4], bf[4][2];
#pragma unroll
            for (int mt = 0; mt < 2; ++mt) {
                int rb = warp_m * 32 + mt * 16;
                af[mt][0] = __float_as_uint(s_s[(rb + g) * SP + kc + t]);
                af[mt][1] = __float_as_uint(s_s[(rb + 8 + g) * SP + kc + t]);
                af[mt][2] = __float_as_uint(s_s[(rb + g) * SP + kc + t + 4]);
                af[mt][3] = __float_as_uint(s_s[(rb + 8 + g) * SP + kc + t + 4]);
            }
#pragma unroll
            for (int nt = 0; nt < 4; ++nt) {
                int cb = warp_n * 32 + nt * 8;
                bf[nt][0] = __float_as_uint(v_s[(kc + t) * SP + cb + g]);
                bf[nt][1] = __float_as_uint(v_s[(kc + t + 4) * SP + cb + g]);
            }
#pragma unroll
            for (int mt = 0; mt < 2; ++mt)
#pragma unroll
                for (int nt = 0; nt < 4; ++nt)
                    mma8(acc[mt][nt][0], acc[mt][nt][1], acc[mt][nt][2], acc[mt][nt][3],
                         af[mt][0], af[mt][1], af[mt][2], af[mt][3],
                         bf[nt][0], bf[nt][1]);
        }
    }

    // ---- epilogue: /l, *gate, store ----
#pragma unroll
    for (int mt = 0; mt < 2; ++mt) {
#pragma unroll
        for (int nt = 0; nt < 4; ++nt) {
            int rl0 = warp_m * 32 + mt * 16 + g;
            int cb  = warp_n * 32 + nt * 8 + 2 * t;
            float inv0 = 1.f / l_sm[rl0];
            float inv1 = 1.f / l_sm[rl0 + 8];
            size_t base0 = ((size_t)(b * LSEQ + q0 + rl0)) * NCOLS + h * DHEAD;
            size_t base1 = ((size_t)(b * LSEQ + q0 + rl0 + 8)) * NCOLS + h * DHEAD;
            g_att[base0 + cb]     = acc[mt][nt][0] * inv0 * g_gate[base0 + cb];
            g_att[base0 + cb + 1] = acc[mt][nt][1] * inv0 * g_gate[base0 + cb + 1];
            g_att[base1 + cb]     = acc[mt][nt][2] * inv1 * g_gate[base1 + cb];
            g_att[base1 + cb + 1] = acc[mt][nt][3] * inv1 * g_gate[base1 + cb + 1];
        }
    }
}

// ================= Output projection =================
__global__ __launch_bounds__(256)
void oproj_kernel(const float* __restrict__ Wo, const float* __restrict__ obias,
                  float* __restrict__ out)
{
    __shared__ float As[GBM * APITCH];
    __shared__ float Bs[GBK * BPITCH];

    const int row0 = blockIdx.y * GBM;
    const int col0 = blockIdx.x * GBN;
    const int tid = threadIdx.x;
    const int lane = tid & 31, wid = tid >> 5;
    const int g = lane >> 2, t = lane & 3;
    const int warp_m = wid & 3, warp_n = wid >> 2;

    float acc[2][4][4];
#pragma unroll
    for (int mt = 0; mt < 2; ++mt)
#pragma unroll
        for (int nt = 0; nt < 4; ++nt)
#pragma unroll
            for (int e = 0; e < 4; ++e) acc[mt][nt][e] = 0.f;

    for (int k0 = 0; k0 < NCOLS; k0 += GBK) {
#pragma unroll
        for (int i = 0; i < 2; ++i) {
            int idx = tid + i * 256;
            int r = idx >> 2, kq = (idx & 3) * 4;
            float4 v4 = *reinterpret_cast<const float4*>(
                &g_att[(size_t)(row0 + r) * NCOLS + k0 + kq]);
            float* dst = &As[r * APITCH + kq];
            dst[0] = tf32r(v4.x); dst[1] = tf32r(v4.y);
            dst[2] = tf32r(v4.z); dst[3] = tf32r(v4.w);
        }
        {
            int kk = tid >> 4, nq = (tid & 15) * 4;
            float4 v4 = *reinterpret_cast<const float4*>(
                &Wo[(size_t)(k0 + kk) * DMODEL + col0 + nq]);
            float* dst = &Bs[kk * BPITCH + nq];
            dst[0] = tf32r(v4.x); dst[1] = tf32r(v4.y);
            dst[2] = tf32r(v4.z); dst[3] = tf32r(v4.w);
        }
        __syncthreads();

#pragma unroll
        for (int kc = 0; kc < GBK; kc += 8) {
            uint32_t af[2][4], bf[4][2];
#pragma unroll
            for (int mt = 0; mt < 2; ++mt) {
                int rb = warp_m * 32 + mt * 16;
                af[mt][0] = __float_as_uint(As[(rb + g) * APITCH + kc + t]);
                af[mt][1] = __float_as_uint(As[(rb + 8 + g) * APITCH + kc + t]);
                af[mt][2] = __float_as_uint(As[(rb + g) * APITCH + kc + t + 4]);
                af[mt][3] = __float_as_uint(As[(rb + 8 + g) * APITCH + kc + t + 4]);
            }
#pragma unroll
            for (int nt = 0; nt < 4; ++nt) {
                int cb = warp_n * 32 + nt * 8;
                bf[nt][0] = __float_as_uint(Bs[(kc + t) * BPITCH + cb + g]);
                bf[nt][1] = __float_as_uint(Bs[(kc + t + 4) * BPITCH + cb + g]);
            }
#pragma unroll
            for (int mt = 0; mt < 2; ++mt)
#pragma unroll
                for (int nt = 0; nt < 4; ++nt)
                    mma8(acc[mt][nt][0], acc[mt][nt][1], acc[mt][nt][2], acc[mt][nt][3],
                         af[mt][0], af[mt][1], af[mt][2], af[mt][3],
                         bf[nt][0], bf[nt][1]);
        }
        __syncthreads();
    }

#pragma unroll
    for (int mt = 0; mt < 2; ++mt) {
#pragma unroll
        for (int nt = 0; nt < 4; ++nt) {
            int rg0 = row0 + warp_m * 32 + mt * 16 + g;
            int cg  = col0 + warp_n * 32 + nt * 8 + 2 * t;
            out[(size_t)rg0 * DMODEL + cg]           = acc[mt][nt][0] + obias[cg];
            out[(size_t)rg0 * DMODEL + cg + 1]       = acc[mt][nt][1] + obias[cg + 1];
            out[(size_t)(rg0 + 8) * DMODEL + cg]     = acc[mt][nt][2] + obias[cg];
            out[(size_t)(rg0 + 8) * DMODEL + cg + 1] = acc[mt][nt][3] + obias[cg + 1];
        }
    }
}

// ================= launcher =================
extern "C" void kernel_launch(void* const* d_in, const int* in_sizes, int n_in,
                              void* d_out, int out_size)
{
    const float*   Q    = (const float*)d_in[0];
    const float*   K    = (const float*)d_in[1];
    const float*   V    = (const float*)d_in[2];
    const float*   bias = (const float*)d_in[3];
    const int*     mask = (const int*)d_in[4];
    const float*   qw   = (const float*)d_in[5];
    const float*   kw   = (const float*)d_in[6];
    const float*   vw   = (const float*)d_in[7];
    const float*   gw   = (const float*)d_in[8];
    const float*   gb   = (const float*)d_in[9];
    const float*   ow   = (const float*)d_in[10];
    const float*   ob   = (const float*)d_in[11];
    float* out = (float*)d_out;

    cudaFuncSetAttribute(attn_kernel, cudaFuncAttributeMaxDynamicSharedMemorySize,
                         ATTN_SMEM_BYTES);

    dim3 gp(NCOLS / GBN, MROWS / GBM, 4);      // 16 x 32 x 4
    proj_kernel<<<gp, 256>>>(Q, K, V, qw, kw, vw, gw, gb);

    dim3 ga(LSEQ / BQ, NHEAD, NBATCH);         // 16 x 16 x 2
    attn_kernel<<<ga, 256, ATTN_SMEM_BYTES>>>(bias, mask);

    dim3 go(DMODEL / GBN, MROWS / GBM, 1);     // 16 x 32
    oproj_kernel<<<go, 256>>>(ow, ob, out);
}